// round 4
// baseline (speedup 1.0000x reference)
#include <cuda_runtime.h>
#include <cstdint>
#include <cstddef>

// Problem constants
constexpr int Bb  = 2;
constexpr int Ss  = 2048;
constexpr int Dd  = 4096;
constexpr int NH  = 32;
constexpr int NKV = 8;
constexpr int HD  = 128;
constexpr int TOK = Bb * Ss;     // 4096 tokens
constexpr int QD  = NH * HD;     // 4096
constexpr int KD  = NKV * HD;    // 1024

// Scratch (allocation-free rule: __device__ globals)
__device__ float g_q[TOK * QD];      // 64 MB
__device__ float g_k[TOK * KD];      // 16 MB
__device__ float g_v[TOK * KD];      // 16 MB
__device__ float g_attn[TOK * QD];   // 64 MB

// ---------------------------------------------------------------------------
// SGEMM: C[M,N] = A[M,K] * B[K,N], all row-major, fp32.
// 128x128 tile, BK=16, 256 threads, 8x8 per-thread microtile.
// Double-buffered smem: one __syncthreads per K-step; iteration t reads
// buffer (t&1) while filling buffer (t&1)^1.
// Requires M%128==0, N%128==0, K%32==0 (true for all uses here).
// ---------------------------------------------------------------------------
__global__ __launch_bounds__(256) void sgemm128(
    const float* __restrict__ A, const float* __restrict__ B,
    float* __restrict__ C, int M, int N, int K)
{
    __shared__ float As[2][16][128];   // transposed A tile: As[buf][k][m]
    __shared__ float Bs[2][16][128];   // Bs[buf][k][n]

    const int tid = threadIdx.x;
    const int tx  = tid & 15;
    const int ty  = tid >> 4;
    const int bn  = blockIdx.x * 128;
    const int bm  = blockIdx.y * 128;

    const float* Ab = A + (size_t)bm * K;
    const float* Bp = B + bn;

    float acc[8][8];
#pragma unroll
    for (int i = 0; i < 8; i++)
#pragma unroll
        for (int j = 0; j < 8; j++) acc[i][j] = 0.f;

    const int T = K / 16;

    // Preload tile 0 into buffer 0
#pragma unroll
    for (int it = 0; it < 2; it++) {
        int f  = tid + it * 256;
        int r  = f >> 2;
        int g4 = (f & 3) * 4;
        float4 av = *(const float4*)(Ab + (size_t)r * K + g4);
        As[0][g4 + 0][r] = av.x;
        As[0][g4 + 1][r] = av.y;
        As[0][g4 + 2][r] = av.z;
        As[0][g4 + 3][r] = av.w;
        int rb = f >> 5;
        int cb = (f & 31) * 4;
        *(float4*)(&Bs[0][rb][cb]) = *(const float4*)(Bp + (size_t)rb * N + cb);
    }
    __syncthreads();

    for (int t = 0; t < T; t++) {
        const int cur = t & 1;
        const int nxt = cur ^ 1;

        // Issue loads for the next tile first (into the other buffer)
        if (t + 1 < T) {
            int kk = (t + 1) * 16;
#pragma unroll
            for (int it = 0; it < 2; it++) {
                int f  = tid + it * 256;
                int r  = f >> 2;
                int g4 = (f & 3) * 4;
                float4 av = *(const float4*)(Ab + (size_t)r * K + kk + g4);
                As[nxt][g4 + 0][r] = av.x;
                As[nxt][g4 + 1][r] = av.y;
                As[nxt][g4 + 2][r] = av.z;
                As[nxt][g4 + 3][r] = av.w;
                int rb = f >> 5;
                int cb = (f & 31) * 4;
                *(float4*)(&Bs[nxt][rb][cb]) =
                    *(const float4*)(Bp + (size_t)(kk + rb) * N + cb);
            }
        }

        // Compute on the current buffer
#pragma unroll
        for (int k = 0; k < 16; k++) {
            float a[8], b[8];
            *(float4*)(&a[0]) = *(const float4*)(&As[cur][k][ty * 4]);
            *(float4*)(&a[4]) = *(const float4*)(&As[cur][k][64 + ty * 4]);
            *(float4*)(&b[0]) = *(const float4*)(&Bs[cur][k][tx * 4]);
            *(float4*)(&b[4]) = *(const float4*)(&Bs[cur][k][64 + tx * 4]);
#pragma unroll
            for (int i = 0; i < 8; i++)
#pragma unroll
                for (int j = 0; j < 8; j++)
                    acc[i][j] = fmaf(a[i], b[j], acc[i][j]);
        }
        __syncthreads();   // nxt fully written; cur fully read
    }

#pragma unroll
    for (int i = 0; i < 8; i++) {
        int row = bm + ((i < 4) ? (ty * 4 + i) : (64 + ty * 4 + (i - 4)));
        float4 v0 = make_float4(acc[i][0], acc[i][1], acc[i][2], acc[i][3]);
        float4 v1 = make_float4(acc[i][4], acc[i][5], acc[i][6], acc[i][7]);
        *(float4*)(C + (size_t)row * N + bn + tx * 4)      = v0;
        *(float4*)(C + (size_t)row * N + bn + 64 + tx * 4) = v1;
    }
}

// ---------------------------------------------------------------------------
// RoPE (interleaved pairs), in-place on [TOK][heads*HD].
// ---------------------------------------------------------------------------
__global__ void rope_kernel(float* __restrict__ t,
                            const float* __restrict__ cosb,
                            const float* __restrict__ sinb,
                            int heads, int total)
{
    int idx = blockIdx.x * blockDim.x + threadIdx.x;
    if (idx >= total) return;
    int d2   = idx & 63;
    int rest = idx >> 6;
    int hh   = rest % heads;
    int tok  = rest / heads;
    int pos  = tok & (Ss - 1);          // token % S
    float cv = cosb[pos * 64 + d2];
    float sv = sinb[pos * 64 + d2];
    float2* p = (float2*)(t + (size_t)tok * heads * HD + hh * HD + d2 * 2);
    float2 v = *p;
    *p = make_float2(v.x * cv - v.y * sv, v.x * sv + v.y * cv);
}

// ---------------------------------------------------------------------------
// Flash attention, fp32, causal, GQA (q head h -> kv head h/4).
// Grid: (S/64, NH, B). 256 threads (16x16). BQ=BK=64, HD=128.
// ---------------------------------------------------------------------------
constexpr int FLASH_SMEM_FLOATS = 64 * 128 + 64 * 129 + 64 * 129 + 64 * 65 + 64 * 3;
constexpr int FLASH_SMEM = FLASH_SMEM_FLOATS * 4;   // 116224 B

__global__ __launch_bounds__(256) void flash_kernel(
    const float* __restrict__ Q, const float* __restrict__ K,
    const float* __restrict__ V, float* __restrict__ O)
{
    extern __shared__ float sm[];
    float* Qs    = sm;                  // [64][128]
    float* Ks    = Qs + 64 * 128;       // [64][129]
    float* Vs    = Ks + 64 * 129;       // [64][129]
    float* Ps    = Vs + 64 * 129;       // [64][65]
    float* row_m = Ps + 64 * 65;        // [64]
    float* row_l = row_m + 64;          // [64]
    float* row_f = row_l + 64;          // [64]

    const int tid = threadIdx.x;
    const int tx  = tid & 15;
    const int ty  = tid >> 4;
    const int qb  = blockIdx.x;
    const int h   = blockIdx.y;
    const int b   = blockIdx.z;
    const int g   = h >> 2;             // kv head
    const int q0  = qb * 64;
    const float scale = 0.08838834764831845f;   // 1/sqrt(128)

    const float* Qg = Q + (size_t)(b * Ss + q0) * QD + h * HD;
    const float* Kg = K + (size_t)(b * Ss) * KD + g * HD;
    const float* Vg = V + (size_t)(b * Ss) * KD + g * HD;

    // Load Q tile (64x128) with float4
#pragma unroll
    for (int i = 0; i < 8; i++) {
        int f  = tid + i * 256;
        int r  = f >> 5;
        int c4 = (f & 31) * 4;
        *(float4*)(&Qs[r * 128 + c4]) = *(const float4*)(Qg + (size_t)r * QD + c4);
    }
    if (tid < 64) { row_m[tid] = -1e30f; row_l[tid] = 0.f; }

    float acc[4][8];
#pragma unroll
    for (int i = 0; i < 4; i++)
#pragma unroll
        for (int j = 0; j < 8; j++) acc[i][j] = 0.f;

    for (int kt = 0; kt <= qb; kt++) {
        __syncthreads();   // protects Qs init (iter 0) and Ks/Vs/Ps reuse
        // Load K,V tiles (64x128 each)
#pragma unroll
        for (int i = 0; i < 8; i++) {
            int f  = tid + i * 256;
            int r  = f >> 5;
            int c4 = (f & 31) * 4;
            float4 kv = *(const float4*)(Kg + (size_t)(kt * 64 + r) * KD + c4);
            Ks[r * 129 + c4 + 0] = kv.x;
            Ks[r * 129 + c4 + 1] = kv.y;
            Ks[r * 129 + c4 + 2] = kv.z;
            Ks[r * 129 + c4 + 3] = kv.w;
            float4 vv = *(const float4*)(Vg + (size_t)(kt * 64 + r) * KD + c4);
            Vs[r * 129 + c4 + 0] = vv.x;
            Vs[r * 129 + c4 + 1] = vv.y;
            Vs[r * 129 + c4 + 2] = vv.z;
            Vs[r * 129 + c4 + 3] = vv.w;
        }
        __syncthreads();

        // Scores: 4x4 per thread. S[r][c] = sum_d Q[r][d]*K[c][d]
        float s4[4][4];
#pragma unroll
        for (int i = 0; i < 4; i++)
#pragma unroll
            for (int j = 0; j < 4; j++) s4[i][j] = 0.f;

#pragma unroll 8
        for (int d = 0; d < 128; d++) {
            float qv[4], kv[4];
#pragma unroll
            for (int i = 0; i < 4; i++) qv[i] = Qs[(ty * 4 + i) * 128 + d];
#pragma unroll
            for (int j = 0; j < 4; j++) kv[j] = Ks[(tx * 4 + j) * 129 + d];
#pragma unroll
            for (int i = 0; i < 4; i++)
#pragma unroll
                for (int j = 0; j < 4; j++)
                    s4[i][j] = fmaf(qv[i], kv[j], s4[i][j]);
        }

        // Scale + causal mask (diagonal tile only) + write to smem
#pragma unroll
        for (int i = 0; i < 4; i++)
#pragma unroll
            for (int j = 0; j < 4; j++) {
                float val = s4[i][j] * scale;
                if (kt == qb && (tx * 4 + j) > (ty * 4 + i)) val = -1e30f;
                Ps[(ty * 4 + i) * 65 + tx * 4 + j] = val;
            }
        __syncthreads();

        // Online softmax: 4 threads per row (16 elements each)
        {
            int r   = tid >> 2;
            int seg = tid & 3;
            float* pr = Ps + r * 65 + seg * 16;
            float mx = -1e30f;
#pragma unroll
            for (int j = 0; j < 16; j++) mx = fmaxf(mx, pr[j]);
            mx = fmaxf(mx, __shfl_xor_sync(0xffffffffu, mx, 1));
            mx = fmaxf(mx, __shfl_xor_sync(0xffffffffu, mx, 2));
            float m_old = row_m[r];
            float m_new = fmaxf(m_old, mx);
            float sum = 0.f;
#pragma unroll
            for (int j = 0; j < 16; j++) {
                float e = __expf(pr[j] - m_new);
                pr[j] = e;
                sum += e;
            }
            sum += __shfl_xor_sync(0xffffffffu, sum, 1);
            sum += __shfl_xor_sync(0xffffffffu, sum, 2);
            if (seg == 0) {
                float fac = __expf(m_old - m_new);
                row_f[r] = fac;
                row_l[r] = row_l[r] * fac + sum;
                row_m[r] = m_new;
            }
        }
        __syncthreads();

        // Rescale accumulators, then O += P @ V
        float fr[4];
#pragma unroll
        for (int i = 0; i < 4; i++) fr[i] = row_f[ty * 4 + i];
#pragma unroll
        for (int i = 0; i < 4; i++)
#pragma unroll
            for (int j = 0; j < 8; j++) acc[i][j] *= fr[i];

#pragma unroll 4
        for (int k = 0; k < 64; k++) {
            float pv[4], vv[8];
#pragma unroll
            for (int i = 0; i < 4; i++) pv[i] = Ps[(ty * 4 + i) * 65 + k];
#pragma unroll
            for (int j = 0; j < 4; j++) {
                vv[j]     = Vs[k * 129 + tx * 4 + j];
                vv[4 + j] = Vs[k * 129 + 64 + tx * 4 + j];
            }
#pragma unroll
            for (int i = 0; i < 4; i++)
#pragma unroll
                for (int j = 0; j < 8; j++)
                    acc[i][j] = fmaf(pv[i], vv[j], acc[i][j]);
        }
    }

    // Epilogue: divide by l and store to attention buffer [tok][h*128 + d]
    float li[4];
#pragma unroll
    for (int i = 0; i < 4; i++) li[i] = 1.f / row_l[ty * 4 + i];
    float* Og = O + (size_t)(b * Ss + q0) * QD + h * HD;
#pragma unroll
    for (int i = 0; i < 4; i++) {
        int r = ty * 4 + i;
#pragma unroll
        for (int j = 0; j < 4; j++) {
            Og[(size_t)r * QD + tx * 4 + j]      = acc[i][j]     * li[i];
            Og[(size_t)r * QD + 64 + tx * 4 + j] = acc[i][4 + j] * li[i];
        }
    }
}

// ---------------------------------------------------------------------------
// Launch
// ---------------------------------------------------------------------------
extern "C" void kernel_launch(void* const* d_in, const int* in_sizes, int n_in,
                              void* d_out, int out_size)
{
    const float* x  = (const float*)d_in[0];
    const float* fc = (const float*)d_in[1];
    const float* fs = (const float*)d_in[2];
    const float* wq = (const float*)d_in[3];
    const float* wk = (const float*)d_in[4];
    const float* wv = (const float*)d_in[5];
    const float* wo = (const float*)d_in[6];
    float* out = (float*)d_out;

    float *q, *k, *v, *attn;
    cudaGetSymbolAddress((void**)&q, g_q);
    cudaGetSymbolAddress((void**)&k, g_k);
    cudaGetSymbolAddress((void**)&v, g_v);
    cudaGetSymbolAddress((void**)&attn, g_attn);

    cudaFuncSetAttribute(flash_kernel,
                         cudaFuncAttributeMaxDynamicSharedMemorySize, FLASH_SMEM);

    // QKV projections
    sgemm128<<<dim3(QD / 128, TOK / 128), 256>>>(x, wq, q, TOK, QD, Dd);
    sgemm128<<<dim3(KD / 128, TOK / 128), 256>>>(x, wk, k, TOK, KD, Dd);
    sgemm128<<<dim3(KD / 128, TOK / 128), 256>>>(x, wv, v, TOK, KD, Dd);

    // RoPE on Q and K
    rope_kernel<<<(TOK * NH * 64 + 255) / 256, 256>>>(q, fc, fs, NH, TOK * NH * 64);
    rope_kernel<<<(TOK * NKV * 64 + 255) / 256, 256>>>(k, fc, fs, NKV, TOK * NKV * 64);

    // Causal GQA attention
    flash_kernel<<<dim3(Ss / 64, NH, Bb), 256, FLASH_SMEM>>>(q, k, v, attn);

    // Output projection -> d_out
    sgemm128<<<dim3(Dd / 128, TOK / 128), 256>>>(attn, wo, out, TOK, Dd, QD);
}

// round 6
// speedup vs baseline: 1.4679x; 1.4679x over previous
#include <cuda_runtime.h>
#include <cuda_bf16.h>
#include <cstdint>
#include <cstddef>

// Problem constants
constexpr int Bb  = 2;
constexpr int Ss  = 2048;
constexpr int Dd  = 4096;
constexpr int NH  = 32;
constexpr int NKV = 8;
constexpr int HD  = 128;
constexpr int TOK = Bb * Ss;     // 4096 tokens
constexpr int QD  = NH * HD;     // 4096
constexpr int KD  = NKV * HD;    // 1024
constexpr int GK  = 4096;        // K dim of every GEMM (D and QD)

// fp32 scratch
__device__ __align__(16) float g_q[TOK * QD];
__device__ __align__(16) float g_k[TOK * KD];
__device__ __align__(16) float g_v[TOK * KD];
__device__ __align__(16) float g_attn[TOK * QD];

// bf16 split scratch (hi/lo)
__device__ __align__(16) __nv_bfloat16 g_xh[TOK * Dd],  g_xl[TOK * Dd];
__device__ __align__(16) __nv_bfloat16 g_wqh[QD * Dd],  g_wql[QD * Dd];   // transposed [N][K]
__device__ __align__(16) __nv_bfloat16 g_wkh[KD * Dd],  g_wkl[KD * Dd];
__device__ __align__(16) __nv_bfloat16 g_wvh[KD * Dd],  g_wvl[KD * Dd];
__device__ __align__(16) __nv_bfloat16 g_woh[Dd * QD],  g_wol[Dd * QD];   // transposed [N=D][K=QD]
__device__ __align__(16) __nv_bfloat16 g_ah[TOK * QD],  g_al[TOK * QD];

// ---------------------------------------------------------------------------
// mma.sync helpers (sm_80-class PTX — compiles under compute_103)
// ---------------------------------------------------------------------------
__device__ __forceinline__ uint32_t smem_u32(const void* p) {
    uint32_t a;
    asm("{ .reg .u64 t; cvta.to.shared.u64 t, %1; cvt.u32.u64 %0, t; }"
        : "=r"(a) : "l"(p));
    return a;
}
__device__ __forceinline__ void ldsm4(uint32_t* r, uint32_t addr) {
    asm volatile("ldmatrix.sync.aligned.m8n8.x4.shared.b16 {%0,%1,%2,%3}, [%4];"
                 : "=r"(r[0]), "=r"(r[1]), "=r"(r[2]), "=r"(r[3]) : "r"(addr));
}
__device__ __forceinline__ void mma16816(float* c, const uint32_t* a, const uint32_t* b) {
    asm volatile("mma.sync.aligned.m16n8k16.row.col.f32.bf16.bf16.f32 "
                 "{%0,%1,%2,%3}, {%4,%5,%6,%7}, {%8,%9}, {%0,%1,%2,%3};"
                 : "+f"(c[0]), "+f"(c[1]), "+f"(c[2]), "+f"(c[3])
                 : "r"(a[0]), "r"(a[1]), "r"(a[2]), "r"(a[3]), "r"(b[0]), "r"(b[1]));
}

// ---------------------------------------------------------------------------
// Tensor-core GEMM, bf16x3 split. C[M,N] = A*B^T where
// A = Ah+Al [M][GK] bf16 K-major, B = Bh+Bl [N][GK] bf16 K-major.
// CTA tile 128x128, BK=64 bf16, 256 threads (8 warps, 2x4), warp tile 64x32.
// Smem rows padded to 72 bf16 (144B) -> LDSM conflict-free.
// ---------------------------------------------------------------------------
constexpr int BK       = 64;                 // bf16 K elements per chunk
constexpr int NCH      = GK / BK;            // 64
constexpr int RSB      = 144;                // smem row stride bytes (72 bf16)
constexpr int TILE_B   = 128 * RSB;          // 18432 B per tile
constexpr int BUF_B    = 4 * TILE_B;         // Ah, Al, Bh, Bl
constexpr int GEMM_SMEM = 2 * BUF_B;         // 147456 B

__global__ __launch_bounds__(256) void gemm_bf16x3(
    const __nv_bfloat16* __restrict__ Ah, const __nv_bfloat16* __restrict__ Al,
    const __nv_bfloat16* __restrict__ Bh, const __nv_bfloat16* __restrict__ Bl,
    float* __restrict__ C, int N)
{
    extern __shared__ char smem[];
    const uint32_t sb = smem_u32(smem);
    const int tid = threadIdx.x;
    const int wid = tid >> 5;
    const int lid = tid & 31;
    const int wm  = wid & 1;          // warp row (2)
    const int wn  = wid >> 1;         // warp col (4)
    const int bn  = blockIdx.x * 128;
    const int bm  = blockIdx.y * 128;

    // Source row-base pointers (bytes); row stride = GK*2 = 8192 bytes
    const char* srcs[4] = {
        (const char*)Ah + (size_t)bm * GK * 2,
        (const char*)Al + (size_t)bm * GK * 2,
        (const char*)Bh + (size_t)bn * GK * 2,
        (const char*)Bl + (size_t)bn * GK * 2
    };

    // Load chunk c (BK=64 bf16 = 128 bytes per row) into buffer buf
    auto load_chunk = [&](int c, int buf) {
        const size_t coff = (size_t)c * 128;
#pragma unroll
        for (int t = 0; t < 4; t++) {
            char* dst = smem + buf * BUF_B + t * TILE_B;
            const char* src = srcs[t] + coff;
#pragma unroll
            for (int i = 0; i < 4; i++) {
                int f   = tid + i * 256;          // 0..1023
                int row = f >> 3;                 // 0..127
                int c16 = (f & 7) * 16;           // 0..112 bytes
                uint4 v = *(const uint4*)(src + (size_t)row * (GK * 2) + c16);
                *(uint4*)(dst + row * RSB + c16) = v;
            }
        }
    };

    // Per-lane ldmatrix base offsets
    const int aRow  = wm * 64 + (lid & 15);           // + mt*16
    const int aKoff = (lid >> 4) * 8;                 // + k0
    const int bRow  = wn * 32 + ((lid >> 4) << 3) + (lid & 7);   // + p*16
    const int bKoff = ((lid >> 3) & 1) * 8;           // + k0

    float acc[4][4][4];
#pragma unroll
    for (int mt = 0; mt < 4; mt++)
#pragma unroll
        for (int nt = 0; nt < 4; nt++)
#pragma unroll
            for (int r = 0; r < 4; r++) acc[mt][nt][r] = 0.f;

    load_chunk(0, 0);
    __syncthreads();

    for (int c = 0; c < NCH; c++) {
        const int cur = c & 1;
        if (c + 1 < NCH) load_chunk(c + 1, cur ^ 1);

        const uint32_t base   = sb + cur * BUF_B;
        const uint32_t tAh    = base;
        const uint32_t tAl    = base + TILE_B;
        const uint32_t tBh    = base + 2 * TILE_B;
        const uint32_t tBl    = base + 3 * TILE_B;

#pragma unroll
        for (int ks = 0; ks < 4; ks++) {
            const int k0 = ks * 16;
            uint32_t ah[4][4], al[4][4], bh[4][2], bl[4][2];
#pragma unroll
            for (int mt = 0; mt < 4; mt++) {
                uint32_t addr = tAh + (aRow + mt * 16) * RSB + (k0 + aKoff) * 2;
                ldsm4(ah[mt], addr);
                ldsm4(al[mt], addr + TILE_B);     // Al tile at fixed offset
            }
#pragma unroll
            for (int p = 0; p < 2; p++) {
                uint32_t tmp[4];
                uint32_t addr = tBh + (bRow + p * 16) * RSB + (k0 + bKoff) * 2;
                ldsm4(tmp, addr);
                bh[2 * p][0] = tmp[0]; bh[2 * p][1] = tmp[1];
                bh[2 * p + 1][0] = tmp[2]; bh[2 * p + 1][1] = tmp[3];
                ldsm4(tmp, addr + TILE_B);        // Bl tile
                bl[2 * p][0] = tmp[0]; bl[2 * p][1] = tmp[1];
                bl[2 * p + 1][0] = tmp[2]; bl[2 * p + 1][1] = tmp[3];
            }
#pragma unroll
            for (int mt = 0; mt < 4; mt++)
#pragma unroll
                for (int nt = 0; nt < 4; nt++) {
                    mma16816(acc[mt][nt], ah[mt], bh[nt]);   // hi*hi
                    mma16816(acc[mt][nt], ah[mt], bl[nt]);   // hi*lo
                    mma16816(acc[mt][nt], al[mt], bh[nt]);   // lo*hi
                }
        }
        __syncthreads();
    }

    // Epilogue: fragment layout -> C
    const int grp  = lid >> 2;
    const int tid4 = lid & 3;
#pragma unroll
    for (int mt = 0; mt < 4; mt++) {
        const int row0 = bm + wm * 64 + mt * 16 + grp;
#pragma unroll
        for (int nt = 0; nt < 4; nt++) {
            const int col = bn + wn * 32 + nt * 8 + tid4 * 2;
            *(float2*)(C + (size_t)row0 * N + col) =
                make_float2(acc[mt][nt][0], acc[mt][nt][1]);
            *(float2*)(C + (size_t)(row0 + 8) * N + col) =
                make_float2(acc[mt][nt][2], acc[mt][nt][3]);
        }
    }
}

// ---------------------------------------------------------------------------
// fp32 -> bf16 hi/lo split (elementwise)
// ---------------------------------------------------------------------------
__global__ void split_bf16(const float* __restrict__ src,
                           __nv_bfloat16* __restrict__ hi,
                           __nv_bfloat16* __restrict__ lo, int n)
{
    int i = blockIdx.x * blockDim.x + threadIdx.x;
    if (i >= n) return;
    float v = src[i];
    __nv_bfloat16 h = __float2bfloat16(v);
    hi[i] = h;
    lo[i] = __float2bfloat16(v - __bfloat162float(h));
}

// ---------------------------------------------------------------------------
// Transpose + split: W [K][N] fp32 -> Wt_hi/lo [N][K] bf16
// ---------------------------------------------------------------------------
__global__ void transpose_split(const float* __restrict__ W,
                                __nv_bfloat16* __restrict__ hi,
                                __nv_bfloat16* __restrict__ lo, int K, int N)
{
    __shared__ float t[32][33];
    const int n0 = blockIdx.x * 32;
    const int k0 = blockIdx.y * 32;
    const int tx = threadIdx.x, ty = threadIdx.y;   // (32, 8)
#pragma unroll
    for (int i = 0; i < 32; i += 8)
        t[ty + i][tx] = W[(size_t)(k0 + ty + i) * N + n0 + tx];
    __syncthreads();
#pragma unroll
    for (int i = 0; i < 32; i += 8) {
        float v = t[tx][ty + i];
        __nv_bfloat16 h = __float2bfloat16(v);
        size_t o = (size_t)(n0 + ty + i) * K + k0 + tx;
        hi[o] = h;
        lo[o] = __float2bfloat16(v - __bfloat162float(h));
    }
}

// ---------------------------------------------------------------------------
// RoPE (interleaved pairs), in-place on [TOK][heads*HD].
// ---------------------------------------------------------------------------
__global__ void rope_kernel(float* __restrict__ t,
                            const float* __restrict__ cosb,
                            const float* __restrict__ sinb,
                            int heads, int total)
{
    int idx = blockIdx.x * blockDim.x + threadIdx.x;
    if (idx >= total) return;
    int d2   = idx & 63;
    int rest = idx >> 6;
    int hh   = rest % heads;
    int tok  = rest / heads;
    int pos  = tok & (Ss - 1);
    float cv = cosb[pos * 64 + d2];
    float sv = sinb[pos * 64 + d2];
    float2* p = (float2*)(t + (size_t)tok * heads * HD + hh * HD + d2 * 2);
    float2 v = *p;
    *p = make_float2(v.x * cv - v.y * sv, v.x * sv + v.y * cv);
}

// ---------------------------------------------------------------------------
// Flash attention, fp32, causal, GQA (unchanged from passing R4 kernel)
// ---------------------------------------------------------------------------
constexpr int FLASH_SMEM_FLOATS = 64 * 128 + 64 * 129 + 64 * 129 + 64 * 65 + 64 * 3;
constexpr int FLASH_SMEM = FLASH_SMEM_FLOATS * 4;

__global__ __launch_bounds__(256) void flash_kernel(
    const float* __restrict__ Q, const float* __restrict__ K,
    const float* __restrict__ V, float* __restrict__ O)
{
    extern __shared__ float sm[];
    float* Qs    = sm;
    float* Ks    = Qs + 64 * 128;
    float* Vs    = Ks + 64 * 129;
    float* Ps    = Vs + 64 * 129;
    float* row_m = Ps + 64 * 65;
    float* row_l = row_m + 64;
    float* row_f = row_l + 64;

    const int tid = threadIdx.x;
    const int tx  = tid & 15;
    const int ty  = tid >> 4;
    const int qb  = blockIdx.x;
    const int h   = blockIdx.y;
    const int b   = blockIdx.z;
    const int g   = h >> 2;
    const int q0  = qb * 64;
    const float scale = 0.08838834764831845f;

    const float* Qg = Q + (size_t)(b * Ss + q0) * QD + h * HD;
    const float* Kg = K + (size_t)(b * Ss) * KD + g * HD;
    const float* Vg = V + (size_t)(b * Ss) * KD + g * HD;

#pragma unroll
    for (int i = 0; i < 8; i++) {
        int f  = tid + i * 256;
        int r  = f >> 5;
        int c4 = (f & 31) * 4;
        *(float4*)(&Qs[r * 128 + c4]) = *(const float4*)(Qg + (size_t)r * QD + c4);
    }
    if (tid < 64) { row_m[tid] = -1e30f; row_l[tid] = 0.f; }

    float acc[4][8];
#pragma unroll
    for (int i = 0; i < 4; i++)
#pragma unroll
        for (int j = 0; j < 8; j++) acc[i][j] = 0.f;

    for (int kt = 0; kt <= qb; kt++) {
        __syncthreads();
#pragma unroll
        for (int i = 0; i < 8; i++) {
            int f  = tid + i * 256;
            int r  = f >> 5;
            int c4 = (f & 31) * 4;
            float4 kv = *(const float4*)(Kg + (size_t)(kt * 64 + r) * KD + c4);
            Ks[r * 129 + c4 + 0] = kv.x;
            Ks[r * 129 + c4 + 1] = kv.y;
            Ks[r * 129 + c4 + 2] = kv.z;
            Ks[r * 129 + c4 + 3] = kv.w;
            float4 vv = *(const float4*)(Vg + (size_t)(kt * 64 + r) * KD + c4);
            Vs[r * 129 + c4 + 0] = vv.x;
            Vs[r * 129 + c4 + 1] = vv.y;
            Vs[r * 129 + c4 + 2] = vv.z;
            Vs[r * 129 + c4 + 3] = vv.w;
        }
        __syncthreads();

        float s4[4][4];
#pragma unroll
        for (int i = 0; i < 4; i++)
#pragma unroll
            for (int j = 0; j < 4; j++) s4[i][j] = 0.f;

#pragma unroll 8
        for (int d = 0; d < 128; d++) {
            float qv[4], kv[4];
#pragma unroll
            for (int i = 0; i < 4; i++) qv[i] = Qs[(ty * 4 + i) * 128 + d];
#pragma unroll
            for (int j = 0; j < 4; j++) kv[j] = Ks[(tx * 4 + j) * 129 + d];
#pragma unroll
            for (int i = 0; i < 4; i++)
#pragma unroll
                for (int j = 0; j < 4; j++)
                    s4[i][j] = fmaf(qv[i], kv[j], s4[i][j]);
        }

#pragma unroll
        for (int i = 0; i < 4; i++)
#pragma unroll
            for (int j = 0; j < 4; j++) {
                float val = s4[i][j] * scale;
                if (kt == qb && (tx * 4 + j) > (ty * 4 + i)) val = -1e30f;
                Ps[(ty * 4 + i) * 65 + tx * 4 + j] = val;
            }
        __syncthreads();

        {
            int r   = tid >> 2;
            int seg = tid & 3;
            float* pr = Ps + r * 65 + seg * 16;
            float mx = -1e30f;
#pragma unroll
            for (int j = 0; j < 16; j++) mx = fmaxf(mx, pr[j]);
            mx = fmaxf(mx, __shfl_xor_sync(0xffffffffu, mx, 1));
            mx = fmaxf(mx, __shfl_xor_sync(0xffffffffu, mx, 2));
            float m_old = row_m[r];
            float m_new = fmaxf(m_old, mx);
            float sum = 0.f;
#pragma unroll
            for (int j = 0; j < 16; j++) {
                float e = __expf(pr[j] - m_new);
                pr[j] = e;
                sum += e;
            }
            sum += __shfl_xor_sync(0xffffffffu, sum, 1);
            sum += __shfl_xor_sync(0xffffffffu, sum, 2);
            if (seg == 0) {
                float fac = __expf(m_old - m_new);
                row_f[r] = fac;
                row_l[r] = row_l[r] * fac + sum;
                row_m[r] = m_new;
            }
        }
        __syncthreads();

        float fr[4];
#pragma unroll
        for (int i = 0; i < 4; i++) fr[i] = row_f[ty * 4 + i];
#pragma unroll
        for (int i = 0; i < 4; i++)
#pragma unroll
            for (int j = 0; j < 8; j++) acc[i][j] *= fr[i];

#pragma unroll 4
        for (int k = 0; k < 64; k++) {
            float pv[4], vv[8];
#pragma unroll
            for (int i = 0; i < 4; i++) pv[i] = Ps[(ty * 4 + i) * 65 + k];
#pragma unroll
            for (int j = 0; j < 4; j++) {
                vv[j]     = Vs[k * 129 + tx * 4 + j];
                vv[4 + j] = Vs[k * 129 + 64 + tx * 4 + j];
            }
#pragma unroll
            for (int i = 0; i < 4; i++)
#pragma unroll
                for (int j = 0; j < 8; j++)
                    acc[i][j] = fmaf(pv[i], vv[j], acc[i][j]);
        }
    }

    float li[4];
#pragma unroll
    for (int i = 0; i < 4; i++) li[i] = 1.f / row_l[ty * 4 + i];
    float* Og = O + (size_t)(b * Ss + q0) * QD + h * HD;
#pragma unroll
    for (int i = 0; i < 4; i++) {
        int r = ty * 4 + i;
#pragma unroll
        for (int j = 0; j < 4; j++) {
            Og[(size_t)r * QD + tx * 4 + j]      = acc[i][j]     * li[i];
            Og[(size_t)r * QD + 64 + tx * 4 + j] = acc[i][4 + j] * li[i];
        }
    }
}

// ---------------------------------------------------------------------------
// Launch
// ---------------------------------------------------------------------------
extern "C" void kernel_launch(void* const* d_in, const int* in_sizes, int n_in,
                              void* d_out, int out_size)
{
    const float* x  = (const float*)d_in[0];
    const float* fc = (const float*)d_in[1];
    const float* fs = (const float*)d_in[2];
    const float* wq = (const float*)d_in[3];
    const float* wk = (const float*)d_in[4];
    const float* wv = (const float*)d_in[5];
    const float* wo = (const float*)d_in[6];
    float* out = (float*)d_out;

    float *q, *k, *v, *attn;
    cudaGetSymbolAddress((void**)&q, g_q);
    cudaGetSymbolAddress((void**)&k, g_k);
    cudaGetSymbolAddress((void**)&v, g_v);
    cudaGetSymbolAddress((void**)&attn, g_attn);
    __nv_bfloat16 *xh, *xl, *wqh, *wql, *wkh, *wkl, *wvh, *wvl, *woh, *wol, *ah, *al;
    cudaGetSymbolAddress((void**)&xh,  g_xh);  cudaGetSymbolAddress((void**)&xl,  g_xl);
    cudaGetSymbolAddress((void**)&wqh, g_wqh); cudaGetSymbolAddress((void**)&wql, g_wql);
    cudaGetSymbolAddress((void**)&wkh, g_wkh); cudaGetSymbolAddress((void**)&wkl, g_wkl);
    cudaGetSymbolAddress((void**)&wvh, g_wvh); cudaGetSymbolAddress((void**)&wvl, g_wvl);
    cudaGetSymbolAddress((void**)&woh, g_woh); cudaGetSymbolAddress((void**)&wol, g_wol);
    cudaGetSymbolAddress((void**)&ah,  g_ah);  cudaGetSymbolAddress((void**)&al,  g_al);

    cudaFuncSetAttribute(flash_kernel,
                         cudaFuncAttributeMaxDynamicSharedMemorySize, FLASH_SMEM);
    cudaFuncSetAttribute(gemm_bf16x3,
                         cudaFuncAttributeMaxDynamicSharedMemorySize, GEMM_SMEM);

    // Input conversions
    split_bf16<<<(TOK * Dd + 255) / 256, 256>>>(x, xh, xl, TOK * Dd);
    transpose_split<<<dim3(QD / 32, Dd / 32), dim3(32, 8)>>>(wq, wqh, wql, Dd, QD);
    transpose_split<<<dim3(KD / 32, Dd / 32), dim3(32, 8)>>>(wk, wkh, wkl, Dd, KD);
    transpose_split<<<dim3(KD / 32, Dd / 32), dim3(32, 8)>>>(wv, wvh, wvl, Dd, KD);

    // QKV projections (tensor-core bf16x3)
    gemm_bf16x3<<<dim3(QD / 128, TOK / 128), 256, GEMM_SMEM>>>(xh, xl, wqh, wql, q, QD);
    gemm_bf16x3<<<dim3(KD / 128, TOK / 128), 256, GEMM_SMEM>>>(xh, xl, wkh, wkl, k, KD);
    gemm_bf16x3<<<dim3(KD / 128, TOK / 128), 256, GEMM_SMEM>>>(xh, xl, wvh, wvl, v, KD);

    // RoPE on Q and K
    rope_kernel<<<(TOK * NH * 64 + 255) / 256, 256>>>(q, fc, fs, NH, TOK * NH * 64);
    rope_kernel<<<(TOK * NKV * 64 + 255) / 256, 256>>>(k, fc, fs, NKV, TOK * NKV * 64);

    // Causal GQA attention (fp32)
    flash_kernel<<<dim3(Ss / 64, NH, Bb), 256, FLASH_SMEM>>>(q, k, v, attn);

    // Output projection (tensor-core bf16x3)
    split_bf16<<<(TOK * QD + 255) / 256, 256>>>(attn, ah, al, TOK * QD);
    transpose_split<<<dim3(Dd / 32, QD / 32), dim3(32, 8)>>>(wo, woh, wol, QD, Dd);
    gemm_bf16x3<<<dim3(Dd / 128, TOK / 128), 256, GEMM_SMEM>>>(ah, al, woh, wol, out, Dd);
}